// round 2
// baseline (speedup 1.0000x reference)
#include <cuda_runtime.h>

// Problem constants
#define B_      64
#define CIN     64
#define COUT    64
#define KP      3
#define T_      300
#define V_      25
#define TT      12          // timesteps per block
#define NCHUNK  (T_/TT)     // 25 chunks
#define P_      (TT*V_)     // 300 pixels per block per channel
#define NTHREADS 192        // 16 c-groups x 12 t
#define NBLK    (B_*NCHUNK) // 1600 blocks
#define NPIX    (B_*T_*V_)  // 480000 elements per channel (BN population)

// Dynamic smem layout (floats)
#define XS_OFF  0                       // x tile: CIN * P_ = 19200
#define WS_OFF  (XS_OFF + CIN*P_)       // W tile (padded stride 65): 64*65 = 4160
#define AS_OFF  (WS_OFF + CIN*65)       // A: 3*25*25 = 1875
#define RED_OFF (AS_OFF + KP*V_*V_)     // stats reduce: 64*12*2 = 1536
#define SMEM_FLOATS (RED_OFF + COUT*TT*2)

// Deterministic BN scratch (static device allocations are allowed)
__device__ float g_part_sum[NBLK*COUT];
__device__ float g_part_sq [NBLK*COUT];
__device__ float g_scale   [COUT];
__device__ float g_shift   [COUT];

extern __shared__ float smem[];

// ---------------------------------------------------------------------------
// Kernel 1: fused 1x1-conv + per-partition graph matmul + BN partial stats
// ---------------------------------------------------------------------------
__global__ __launch_bounds__(NTHREADS, 1)
void sgc_fused_kernel(const float* __restrict__ x,
                      const float* __restrict__ Wg,
                      const float* __restrict__ bias,
                      const float* __restrict__ Ag,
                      float* __restrict__ out)
{
    float* xs  = smem + XS_OFF;
    float* ws  = smem + WS_OFF;
    float* As  = smem + AS_OFF;
    float* red = smem + RED_OFF;

    const int tid   = threadIdx.x;
    const int chunk = blockIdx.x;     // 0..24
    const int b     = blockIdx.y;     // 0..63
    const int t0    = chunk * TT;
    const int cg    = tid & 15;       // c-group: channels cg*4 .. cg*4+3
    const int tq    = tid >> 4;       // local timestep 0..11

    // ---- stage x tile: xs[ci*P_ + p] = x[b, ci, t0 + p/25, p%25] ----
    {
        const float* xbase = x + (size_t)b * (CIN * T_ * V_) + t0 * V_;
        #pragma unroll 4
        for (int i = tid; i < CIN * P_; i += NTHREADS) {
            int ci = i / P_;
            int p  = i - ci * P_;
            xs[i] = xbase[ci * (T_ * V_) + p];
        }
    }
    // ---- stage A ----
    for (int i = tid; i < KP * V_ * V_; i += NTHREADS) As[i] = Ag[i];

    // Output accumulator lives entirely in registers: 4 channels x 25 w
    float oacc[4][V_];
    #pragma unroll
    for (int j = 0; j < 4; ++j)
        #pragma unroll
        for (int w = 0; w < V_; ++w) oacc[j][w] = 0.0f;

    const float* xrow = xs + tq * V_;   // this thread's timestep row base

    #pragma unroll 1
    for (int k = 0; k < KP; ++k) {
        // stage W partition k (transposed, stride-65 pad: conflict-free STS,
        // coalesced LDG). ws[ci*65 + c] = W[(k*64+c)*64 + ci]
        __syncthreads();
        {
            const float* wsrc = Wg + k * (COUT * CIN);
            #pragma unroll 4
            for (int i = tid; i < COUT * CIN; i += NTHREADS) {
                int c  = i >> 6;
                int ci = i & 63;
                ws[ci * 65 + c] = wsrc[i];
            }
        }
        __syncthreads();

        const float b0 = bias[k * COUT + cg * 4 + 0];
        const float b1 = bias[k * COUT + cg * 4 + 1];
        const float b2 = bias[k * COUT + cg * 4 + 2];
        const float b3 = bias[k * COUT + cg * 4 + 3];
        const float* Ak = As + k * (V_ * V_);

        // process v in chunks of 5 to bound live registers
        #pragma unroll 1
        for (int vc = 0; vc < 5; ++vc) {
            const int v0 = vc * 5;
            float y[4][5];
            #pragma unroll
            for (int vv = 0; vv < 5; ++vv) {
                y[0][vv] = b0; y[1][vv] = b1; y[2][vv] = b2; y[3][vv] = b3;
            }
            // conv: y[j][vv] += W[k,c,ci] * x[b,ci,t,v0+vv]
            #pragma unroll 2
            for (int ci = 0; ci < CIN; ++ci) {
                const float w0 = ws[ci * 65 + cg * 4 + 0];
                const float w1 = ws[ci * 65 + cg * 4 + 1];
                const float w2 = ws[ci * 65 + cg * 4 + 2];
                const float w3 = ws[ci * 65 + cg * 4 + 3];
                #pragma unroll
                for (int vv = 0; vv < 5; ++vv) {
                    const float xv = xrow[ci * P_ + v0 + vv];
                    y[0][vv] += w0 * xv;
                    y[1][vv] += w1 * xv;
                    y[2][vv] += w2 * xv;
                    y[3][vv] += w3 * xv;
                }
            }
            // graph stage: oacc[j][w] += sum_vv y[j][vv] * A[k, v0+vv, w]
            #pragma unroll
            for (int w = 0; w < V_; ++w) {
                #pragma unroll
                for (int vv = 0; vv < 5; ++vv) {
                    const float a = Ak[(v0 + vv) * V_ + w];  // uniform broadcast
                    oacc[0][w] += y[0][vv] * a;
                    oacc[1][w] += y[1][vv] * a;
                    oacc[2][w] += y[2][vv] * a;
                    oacc[3][w] += y[3][vv] * a;
                }
            }
        }
    }

    // ---- write pre-BN output directly from registers ----
    {
        const int t = t0 + tq;
        #pragma unroll
        for (int j = 0; j < 4; ++j) {
            float* dst = out + ((size_t)(b * COUT + cg * 4 + j) * T_ + t) * V_;
            #pragma unroll
            for (int w = 0; w < V_; ++w) dst[w] = oacc[j][w];
        }
    }

    // ---- per-block per-channel partial BN stats (deterministic) ----
    #pragma unroll
    for (int j = 0; j < 4; ++j) {
        float s = 0.0f, s2 = 0.0f;
        #pragma unroll
        for (int w = 0; w < V_; ++w) {
            const float v = oacc[j][w];
            s += v; s2 += v * v;
        }
        const int c = cg * 4 + j;
        red[(c * TT + tq) * 2 + 0] = s;
        red[(c * TT + tq) * 2 + 1] = s2;
    }
    __syncthreads();
    if (tid < COUT) {
        const int c = tid;
        float s = 0.0f, s2 = 0.0f;
        #pragma unroll
        for (int q = 0; q < TT; ++q) {
            s  += red[(c * TT + q) * 2 + 0];
            s2 += red[(c * TT + q) * 2 + 1];
        }
        const int blk = b * NCHUNK + chunk;
        g_part_sum[blk * COUT + c] = s;
        g_part_sq [blk * COUT + c] = s2;
    }
}

// ---------------------------------------------------------------------------
// Kernel 2: finalize BN stats (one block per channel, deterministic tree)
// ---------------------------------------------------------------------------
__global__ void sgc_stats_kernel(const float* __restrict__ gamma,
                                 const float* __restrict__ beta)
{
    __shared__ float ss[256];
    __shared__ float ss2[256];
    const int c = blockIdx.x;
    float s = 0.0f, s2 = 0.0f;
    for (int i = threadIdx.x; i < NBLK; i += 256) {
        s  += g_part_sum[i * COUT + c];
        s2 += g_part_sq [i * COUT + c];
    }
    ss[threadIdx.x] = s;
    ss2[threadIdx.x] = s2;
    __syncthreads();
    for (int o = 128; o > 0; o >>= 1) {
        if (threadIdx.x < o) {
            ss[threadIdx.x]  += ss[threadIdx.x + o];
            ss2[threadIdx.x] += ss2[threadIdx.x + o];
        }
        __syncthreads();
    }
    if (threadIdx.x == 0) {
        const float n    = (float)NPIX;
        const float mean = ss[0] / n;
        const float var  = ss2[0] / n - mean * mean;   // biased variance
        const float inv  = rsqrtf(var + 1e-5f);
        const float sc   = gamma[c] * inv;
        g_scale[c] = sc;
        g_shift[c] = beta[c] - mean * sc;
    }
}

// ---------------------------------------------------------------------------
// Kernel 3: in-place normalize, float4 vectorized (7500 % 4 == 0)
// ---------------------------------------------------------------------------
__global__ void sgc_norm_kernel(float* __restrict__ out)
{
    const int i4 = blockIdx.x * blockDim.x + threadIdx.x;  // exactly 7,680,000
    float4* o4 = (float4*)out;
    float4 v = o4[i4];
    const int c = (i4 / (T_ * V_ / 4)) & (COUT - 1);
    const float sc = g_scale[c];
    const float sh = g_shift[c];
    v.x = v.x * sc + sh;
    v.y = v.y * sc + sh;
    v.z = v.z * sc + sh;
    v.w = v.w * sc + sh;
    o4[i4] = v;
}

// ---------------------------------------------------------------------------
extern "C" void kernel_launch(void* const* d_in, const int* in_sizes, int n_in,
                              void* d_out, int out_size)
{
    const float* x     = (const float*)d_in[0];
    const float* W     = (const float*)d_in[1];
    const float* bias  = (const float*)d_in[2];
    const float* A     = (const float*)d_in[3];
    const float* gamma = (const float*)d_in[4];
    const float* beta  = (const float*)d_in[5];
    float* out = (float*)d_out;

    const int smem_bytes = SMEM_FLOATS * (int)sizeof(float);  // ~107 KB
    cudaFuncSetAttribute(sgc_fused_kernel,
                         cudaFuncAttributeMaxDynamicSharedMemorySize, smem_bytes);

    sgc_fused_kernel<<<dim3(NCHUNK, B_), NTHREADS, smem_bytes>>>(x, W, bias, A, out);
    sgc_stats_kernel<<<COUT, 256>>>(gamma, beta);
    // total elements 30,720,000 / 4 = 7,680,000 float4 = 30000 * 256
    sgc_norm_kernel<<<30000, 256>>>(out);
}